// round 16
// baseline (speedup 1.0000x reference)
#include <cuda_runtime.h>
#include <math.h>

#define NV 1024
#define NB 16
#define GRID_DIM 16                 // 16x16 cells of 25m over [0,400)
#define NCELL 256
#define CPB 4                       // cells per block (all in ONE grid row)
#define NBLK (NCELL / CPB)          // 64 blocks per batch
#define THREADS 256

__global__ __launch_bounds__(THREADS)
void rulepolicy_fused(const float* __restrict__ state,
                      const float* __restrict__ lengths,
                      const float* __restrict__ v0p,
                      const float* __restrict__ s0p,
                      const float* __restrict__ dthp,
                      const float* __restrict__ amaxp,
                      const float* __restrict__ bp,
                      float* __restrict__ out)
{
    __shared__ int counts[NCELL];
    __shared__ int offs[NCELL];
    __shared__ int cstart[NCELL + 1];
    __shared__ int wsum[8];
    __shared__ int wsum2[8];
    __shared__ float4 sd[NV];        // region-sorted {x, y, cos, sin}
    __shared__ float  svv[NV];       // region-sorted v
    __shared__ int    sorig[NV];     // region-sorted -> original index

    const int bat = blockIdx.y;
    const int kb  = blockIdx.x;      // owns cells [kb*CPB, kb*CPB+CPB), one row
    const int t = threadIdx.x;
    const int lane = t & 31;
    const int w = t >> 5;
    const float* st = state + (size_t)bat * NV * 5;

    const int cy_own = (kb * CPB) / GRID_DIM;
    const int rowlo = max(cy_own - 2, 0);
    const int rowhi = min(cy_own + 2, GRID_DIM - 1);

    // ── Prep: classify all, sincos+sort ONLY vehicles in rows [rowlo,rowhi] ──
    counts[t] = 0;
    __syncthreads();

    float px[4], py[4];
    int cl[4];
    bool keep[4];
    #pragma unroll
    for (int q = 0; q < 4; q++) {
        int i = t + q * THREADS;
        px[q] = st[i * 5 + 0];
        py[q] = st[i * 5 + 1];
        int cx = max(0, min(GRID_DIM - 1, (int)(px[q] * 0.04f)));
        int cy = max(0, min(GRID_DIM - 1, (int)(py[q] * 0.04f)));
        cl[q] = cy * GRID_DIM + cx;
        keep[q] = (cy >= rowlo) && (cy <= rowhi);
        if (keep[q]) atomicAdd(&counts[cl[q]], 1);
    }
    __syncthreads();

    // Two-level warp-shuffle scan over 256 cells (2 barriers).
    {
        int v = counts[t];
        #pragma unroll
        for (int d = 1; d <= 16; d <<= 1) {
            int o = __shfl_up_sync(0xFFFFFFFFu, v, d);
            if (lane >= d) v += o;
        }
        if (lane == 31) wsum[w] = v;
        __syncthreads();
        if (w == 0) {
            int s = (lane < 8) ? wsum[lane] : 0;
            #pragma unroll
            for (int d = 1; d <= 4; d <<= 1) {
                int o = __shfl_up_sync(0xFFFFFFFFu, s, d);
                if (lane >= d) s += o;
            }
            if (lane < 8) wsum2[lane] = s;
        }
        __syncthreads();
        int add = (w > 0) ? wsum2[w - 1] : 0;
        int inc = v + add;                      // inclusive scan value
        cstart[t + 1] = inc;
        if (t == 0) cstart[0] = 0;
        offs[t] = inc - counts[t];              // exclusive
    }
    __syncthreads();

    #pragma unroll
    for (int q = 0; q < 4; q++) {
        if (keep[q]) {
            int i = t + q * THREADS;
            float vv = st[i * 5 + 2];
            float psi = st[i * 5 + 3];
            float sp, cp;
            sincosf(psi, &sp, &cp);
            int pos = atomicAdd(&offs[cl[q]], 1);
            sd[pos] = make_float4(px[q], py[q], cp, sp);
            svv[pos] = vv;
            sorig[pos] = i;
        }
    }
    __syncthreads();

    // ── Ego processing: warps round-robin over this block's sorted range ──
    const float C20SQ = 0.8830222215594891f;   // cos^2(20deg)
    const float C45   = 0.7071067811865476f;   // cos(45deg)
    const float INF   = __int_as_float(0x7f800000);
    const float TERM  = 46.9f;                 // < 50*cos20 = 46.984

    const float V0 = __ldg(&v0p[0]), S0 = __ldg(&s0p[0]), DTH = __ldg(&dthp[0]);
    const float AMAX = __ldg(&amaxp[0]), BB = __ldg(&bp[0]);
    const float DEN = 2.0f * sqrtf(AMAX * BB);

    const int c0 = cstart[kb * CPB];
    const int c1 = cstart[kb * CPB + CPB];

    for (int p = c0 + w; p < c1; p += THREADS / 32) {
        float4 eg = sd[p];                      // broadcast LDS
        float vj = svv[p];
        float xj = eg.x, yj = eg.y, cj = eg.z, sj = eg.w;
        int cx = max(0, min(GRID_DIM - 1, (int)(xj * 0.04f)));
        int cy = max(0, min(GRID_DIM - 1, (int)(yj * 0.04f)));
        int X0 = max(cx - 2, 0), X1 = min(cx + 2, GRID_DIM - 1);
        int Y0 = max(cy - 2, 0), Y1 = min(cy + 2, GRID_DIM - 1);

        float best = INF;
        int   bidx = 0;
        int   stopi = 0;

        for (int ry = Y0; ry <= Y1; ry++) {
            int beg = cstart[ry * GRID_DIM + X0];
            int end = cstart[ry * GRID_DIM + X1 + 1];
            for (int i = beg + lane; i < end; i += 32) {
                float4 a = sd[i];
                float vi = svv[i];
                float dx = a.x - xj, dy = a.y - yj;
                float r2 = fmaf(dx, dx, dy * dy);
                float nd = fmaf(dx, cj, dy * sj);      // dr*cos(delpsi)
                float n2 = nd * nd;
                float m  = fminf(nd, fmaf(-C20SQ, r2, n2));
                float e  = (m > 0.0f) ? nd : INF;
                bool  c  = e < best;
                best = c ? e : best;  bidx = c ? i : bidx;
                float cpd = fmaf(a.z, cj, a.w * sj);   // cos(psi_i-psi_j)
                // dr<20 & |delpsi|<60 (nd>0 & n2>r2/4) & |dpsi|>45 & v_i>v_j
                stopi |= (int)((r2 < 400.0f) & (nd > 0.0f) & (n2 > 0.25f * r2)
                               & (cpd < C45) & (vi > vj));
            }
        }

        // Warp reductions (REDUX): OR for stop; min float-bits then min index.
        stopi = (int)__reduce_or_sync(0xFFFFFFFFu, (unsigned)stopi);
        unsigned vb = __float_as_uint(best);
        unsigned mn = __reduce_min_sync(0xFFFFFFFFu, vb);
        unsigned cd = (vb == mn) ? (unsigned)bidx : 0xFFFFFFFFu;
        unsigned mi = __reduce_min_sync(0xFFFFFFFFu, cd);
        best = __uint_as_float(mn);
        bidx = (int)mi;

        // Rare fallback: neighborhood couldn't certify (best >= TERM).
        // Rescan ALL vehicles from global state (positions only, identical math).
        bool fellback = false;
        if (best >= TERM) {
            fellback = true;
            float fb = INF; int fi = 0;
            for (int i = lane; i < NV; i += 32) {
                float xx = __ldg(&st[i * 5 + 0]);
                float yy = __ldg(&st[i * 5 + 1]);
                float dx = xx - xj, dy = yy - yj;
                float r2 = fmaf(dx, dx, dy * dy);
                float nd = fmaf(dx, cj, dy * sj);
                float m  = fminf(nd, fmaf(-C20SQ, r2, nd * nd));
                float e  = (m > 0.0f) ? nd : INF;
                bool  c  = e < fb;
                fb = c ? e : fb;  fi = c ? i : fi;
            }
            unsigned vb2 = __float_as_uint(fb);
            unsigned mn2 = __reduce_min_sync(0xFFFFFFFFu, vb2);
            unsigned cd2 = (vb2 == mn2) ? (unsigned)fi : 0xFFFFFFFFu;
            unsigned mi2 = __reduce_min_sync(0xFFFFFFFFu, cd2);
            best = __uint_as_float(mn2);
            bidx = (mi2 == 0xFFFFFFFFu) ? 0 : (int)mi2;   // orig index here
        }

        if (lane == 0) {
            float lc, ls, vl;
            int orig;
            if (fellback) {
                orig = sorig[p];
                vl = __ldg(&st[bidx * 5 + 2]);
                float psil = __ldg(&st[bidx * 5 + 3]);
                sincosf(psil, &ls, &lc);
            } else {
                orig = sorig[p];
                float4 ld = sd[bidx];
                lc = ld.z; ls = ld.w; vl = svv[bidx];
            }
            float dvx = vl * lc - vj * cj;
            float dvy = vl * ls - vj * sj;
            float ndv = fmaf(dvx, cj, dvy * sj);    // dv*cos(vdelpsi)

            float sal   = best - __ldg(&lengths[orig]);
            float sstar = S0 + vj * DTH + (vj * ndv) / DEN;
            float q  = vj / V0;
            float q2 = q * q;
            float afree = AMAX * (1.0f - q2 * q2);

            float action;
            if (stopi) {
                action = afree - AMAX;              // ratio = 1
            } else if (isinf(sal) || isnan(sal)) {
                action = afree;
            } else {
                float r = sstar / sal;
                action = afree - AMAX * r * r;
            }
            out[bat * NV + orig] = action;
        }
    }
}

extern "C" void kernel_launch(void* const* d_in, const int* in_sizes, int n_in,
                              void* d_out, int out_size)
{
    const float* state   = (const float*)d_in[0];
    const float* lengths = (const float*)d_in[1];
    const float* v0      = (const float*)d_in[2];
    const float* s0      = (const float*)d_in[3];
    const float* dth     = (const float*)d_in[4];
    const float* amax    = (const float*)d_in[5];
    const float* b       = (const float*)d_in[6];
    float* out = (float*)d_out;

    dim3 grid(NBLK, NB);
    rulepolicy_fused<<<grid, THREADS>>>(state, lengths, v0, s0, dth, amax, b, out);
}

// round 17
// speedup vs baseline: 1.0124x; 1.0124x over previous
#include <cuda_runtime.h>
#include <math.h>

#define NV 1024
#define NB 16
#define GRID_DIM 16                 // 16x16 cells of 25m over [0,400)
#define NCELL 256
#define CPB 8                       // cells per block (half of ONE grid row)
#define NBLK (NCELL / CPB)          // 32 blocks per batch
#define THREADS 256

__global__ __launch_bounds__(THREADS)
void rulepolicy_fused(const float* __restrict__ state,
                      const float* __restrict__ lengths,
                      const float* __restrict__ v0p,
                      const float* __restrict__ s0p,
                      const float* __restrict__ dthp,
                      const float* __restrict__ amaxp,
                      const float* __restrict__ bp,
                      float* __restrict__ out)
{
    __shared__ int counts[NCELL];
    __shared__ int offs[NCELL];
    __shared__ int cstart[NCELL + 1];
    __shared__ int wsum[8];
    __shared__ int wsum2[8];
    __shared__ float4 sd[NV];        // region-sorted {x, y, cos, sin}
    __shared__ float  svv[NV];       // region-sorted v
    __shared__ int    sorig[NV];     // region-sorted -> original index

    const int bat = blockIdx.y;
    const int kb  = blockIdx.x;      // owns cells [kb*CPB, kb*CPB+CPB), one row
    const int t = threadIdx.x;
    const int lane = t & 31;
    const int w = t >> 5;
    const float* st = state + (size_t)bat * NV * 5;

    const int cy_own = (kb * CPB) / GRID_DIM;     // single row per block
    const int rowlo = max(cy_own - 2, 0);
    const int rowhi = min(cy_own + 2, GRID_DIM - 1);

    // ── Prep: classify all 1024, sincos+sort ONLY rows [rowlo,rowhi] (~5/16) ──
    counts[t] = 0;
    __syncthreads();

    float px[4], py[4];
    int cl[4];
    bool keep[4];
    #pragma unroll
    for (int q = 0; q < 4; q++) {
        int i = t + q * THREADS;
        px[q] = __ldg(&st[i * 5 + 0]);
        py[q] = __ldg(&st[i * 5 + 1]);
        int cx = max(0, min(GRID_DIM - 1, (int)(px[q] * 0.04f)));
        int cy = max(0, min(GRID_DIM - 1, (int)(py[q] * 0.04f)));
        cl[q] = cy * GRID_DIM + cx;
        keep[q] = (cy >= rowlo) && (cy <= rowhi);
        if (keep[q]) atomicAdd(&counts[cl[q]], 1);
    }
    __syncthreads();

    // Two-level warp-shuffle scan over 256 cells (2 barriers).
    {
        int v = counts[t];
        #pragma unroll
        for (int d = 1; d <= 16; d <<= 1) {
            int o = __shfl_up_sync(0xFFFFFFFFu, v, d);
            if (lane >= d) v += o;
        }
        if (lane == 31) wsum[w] = v;
        __syncthreads();
        if (w == 0) {
            int s = (lane < 8) ? wsum[lane] : 0;
            #pragma unroll
            for (int d = 1; d <= 4; d <<= 1) {
                int o = __shfl_up_sync(0xFFFFFFFFu, s, d);
                if (lane >= d) s += o;
            }
            if (lane < 8) wsum2[lane] = s;
        }
        __syncthreads();
        int add = (w > 0) ? wsum2[w - 1] : 0;
        int inc = v + add;                      // inclusive scan value
        cstart[t + 1] = inc;
        if (t == 0) cstart[0] = 0;
        offs[t] = inc - counts[t];              // exclusive
    }
    __syncthreads();

    #pragma unroll
    for (int q = 0; q < 4; q++) {
        if (keep[q]) {
            int i = t + q * THREADS;
            float vv = __ldg(&st[i * 5 + 2]);
            float psi = __ldg(&st[i * 5 + 3]);
            float sp, cp;
            sincosf(psi, &sp, &cp);
            int pos = atomicAdd(&offs[cl[q]], 1);
            sd[pos] = make_float4(px[q], py[q], cp, sp);
            svv[pos] = vv;
            sorig[pos] = i;
        }
    }
    __syncthreads();

    // ── Ego processing: warps round-robin over this block's sorted range ──
    const float C20SQ = 0.8830222215594891f;   // cos^2(20deg)
    const float C45   = 0.7071067811865476f;   // cos(45deg)
    const float INF   = __int_as_float(0x7f800000);
    const float TERM  = 46.9f;                 // < 50*cos20 = 46.984

    const float V0 = __ldg(&v0p[0]), S0 = __ldg(&s0p[0]), DTH = __ldg(&dthp[0]);
    const float AMAX = __ldg(&amaxp[0]), BB = __ldg(&bp[0]);
    const float DEN = 2.0f * sqrtf(AMAX * BB);

    const int c0 = cstart[kb * CPB];
    const int c1 = cstart[kb * CPB + CPB];

    for (int p = c0 + w; p < c1; p += THREADS / 32) {
        float4 eg = sd[p];                      // broadcast LDS
        float vj = svv[p];
        float xj = eg.x, yj = eg.y, cj = eg.z, sj = eg.w;
        int cx = max(0, min(GRID_DIM - 1, (int)(xj * 0.04f)));
        int cy = max(0, min(GRID_DIM - 1, (int)(yj * 0.04f)));
        int X0 = max(cx - 2, 0), X1 = min(cx + 2, GRID_DIM - 1);
        int Y0 = max(cy - 2, 0), Y1 = min(cy + 2, GRID_DIM - 1);

        float best = INF;
        int   bidx = 0;
        int   stopi = 0;

        for (int ry = Y0; ry <= Y1; ry++) {
            int beg = cstart[ry * GRID_DIM + X0];
            int end = cstart[ry * GRID_DIM + X1 + 1];
            for (int i = beg + lane; i < end; i += 32) {
                float4 a = sd[i];
                float vi = svv[i];
                float dx = a.x - xj, dy = a.y - yj;
                float r2 = fmaf(dx, dx, dy * dy);
                float nd = fmaf(dx, cj, dy * sj);      // dr*cos(delpsi)
                float n2 = nd * nd;
                float m  = fminf(nd, fmaf(-C20SQ, r2, n2));
                float e  = (m > 0.0f) ? nd : INF;
                bool  c  = e < best;
                best = c ? e : best;  bidx = c ? i : bidx;
                float cpd = fmaf(a.z, cj, a.w * sj);   // cos(psi_i-psi_j)
                // dr<20 & |delpsi|<60 (nd>0 & n2>r2/4) & |dpsi|>45 & v_i>v_j
                stopi |= (int)((r2 < 400.0f) & (nd > 0.0f) & (n2 > 0.25f * r2)
                               & (cpd < C45) & (vi > vj));
            }
        }

        // Warp reductions (REDUX): OR for stop; min float-bits then min index.
        stopi = (int)__reduce_or_sync(0xFFFFFFFFu, (unsigned)stopi);
        unsigned vb = __float_as_uint(best);
        unsigned mn = __reduce_min_sync(0xFFFFFFFFu, vb);
        unsigned cd = (vb == mn) ? (unsigned)bidx : 0xFFFFFFFFu;
        unsigned mi = __reduce_min_sync(0xFFFFFFFFu, cd);
        best = __uint_as_float(mn);
        bidx = (int)mi;

        // Rare fallback: neighborhood couldn't certify (best >= TERM).
        // Rescan ALL vehicles from global state (positions only, same math).
        bool fellback = false;
        if (best >= TERM) {
            fellback = true;
            float fb = INF; int fi = 0;
            for (int i = lane; i < NV; i += 32) {
                float xx = __ldg(&st[i * 5 + 0]);
                float yy = __ldg(&st[i * 5 + 1]);
                float dx = xx - xj, dy = yy - yj;
                float r2 = fmaf(dx, dx, dy * dy);
                float nd = fmaf(dx, cj, dy * sj);
                float m  = fminf(nd, fmaf(-C20SQ, r2, nd * nd));
                float e  = (m > 0.0f) ? nd : INF;
                bool  c  = e < fb;
                fb = c ? e : fb;  fi = c ? i : fi;
            }
            unsigned vb2 = __float_as_uint(fb);
            unsigned mn2 = __reduce_min_sync(0xFFFFFFFFu, vb2);
            unsigned cd2 = (vb2 == mn2) ? (unsigned)fi : 0xFFFFFFFFu;
            unsigned mi2 = __reduce_min_sync(0xFFFFFFFFu, cd2);
            best = __uint_as_float(mn2);
            bidx = (mi2 == 0xFFFFFFFFu) ? 0 : (int)mi2;   // original index here
        }

        if (lane == 0) {
            float lc, ls, vl;
            int orig = sorig[p];
            if (fellback) {
                vl = __ldg(&st[bidx * 5 + 2]);
                float psil = __ldg(&st[bidx * 5 + 3]);
                sincosf(psil, &ls, &lc);
            } else {
                float4 ld = sd[bidx];
                lc = ld.z; ls = ld.w; vl = svv[bidx];
            }
            float dvx = vl * lc - vj * cj;
            float dvy = vl * ls - vj * sj;
            float ndv = fmaf(dvx, cj, dvy * sj);    // dv*cos(vdelpsi)

            float sal   = best - __ldg(&lengths[orig]);
            float sstar = S0 + vj * DTH + (vj * ndv) / DEN;
            float q  = vj / V0;
            float q2 = q * q;
            float afree = AMAX * (1.0f - q2 * q2);

            float action;
            if (stopi) {
                action = afree - AMAX;              // ratio = 1
            } else if (isinf(sal) || isnan(sal)) {
                action = afree;
            } else {
                float r = sstar / sal;
                action = afree - AMAX * r * r;
            }
            out[bat * NV + orig] = action;
        }
    }
}

extern "C" void kernel_launch(void* const* d_in, const int* in_sizes, int n_in,
                              void* d_out, int out_size)
{
    const float* state   = (const float*)d_in[0];
    const float* lengths = (const float*)d_in[1];
    const float* v0      = (const float*)d_in[2];
    const float* s0      = (const float*)d_in[3];
    const float* dth     = (const float*)d_in[4];
    const float* amax    = (const float*)d_in[5];
    const float* b       = (const float*)d_in[6];
    float* out = (float*)d_out;

    dim3 grid(NBLK, NB);
    rulepolicy_fused<<<grid, THREADS>>>(state, lengths, v0, s0, dth, amax, b, out);
}